// round 1
// baseline (speedup 1.0000x reference)
#include <cuda_runtime.h>

// APPNP: h_{k+1} = (1-a) * Dinv(A+I)Dinv * h_k + a * x,  K=5, a=0.8
// Trick: with g = dinv .* h, aggregation is m[v] = dinv[v]*(g[v] + sum_{e:col=v} g[row_e])
// -> no per-edge weights, only a dst-sorted CSR of row indices.

#define NN 100000
#define EE 1600000
#define DD 48
#define DV 12           // float4 chunks per row (48 floats)
#define ALPHA 0.8f

// ---------------- device scratch (static, no allocation) ----------------
__device__ int    g_ecount[NN];
__device__ float  g_dinv[NN];
__device__ int    g_colptr[NN + 1];
__device__ int    g_cursor[NN];
__device__ int    g_csr_row[EE];
__device__ float4 g_bufA[NN * DV];
__device__ float4 g_bufB[NN * DV];

// ---------------- helpers ----------------
static __device__ __forceinline__ float4 f4add(float4 a, float4 b) {
    return make_float4(a.x + b.x, a.y + b.y, a.z + b.z, a.w + b.w);
}

// ---------------- preprocessing kernels ----------------
__global__ void k_zero_counts() {
    int v = blockIdx.x * blockDim.x + threadIdx.x;
    if (v < NN) g_ecount[v] = 0;
}

__global__ void k_hist(const int* __restrict__ col) {
    int e = blockIdx.x * blockDim.x + threadIdx.x;
    if (e < EE) atomicAdd(&g_ecount[col[e]], 1);
}

__global__ void k_dinv() {
    int v = blockIdx.x * blockDim.x + threadIdx.x;
    if (v < NN) g_dinv[v] = rsqrtf((float)(g_ecount[v] + 1));  // +1 self loop
}

// Single-block exclusive scan of g_ecount -> g_colptr, also seeds g_cursor.
#define SCAN_T 1024
#define SCAN_CHUNK ((NN + SCAN_T - 1) / SCAN_T)   // 98
__global__ void k_scan() {
    __shared__ int sums[SCAN_T];
    int t = threadIdx.x;
    int begin = t * SCAN_CHUNK;
    int end   = begin + SCAN_CHUNK;
    if (end > NN) end = NN;

    int s = 0;
    for (int i = begin; i < end; i++) s += g_ecount[i];
    sums[t] = s;
    __syncthreads();

    // Hillis-Steele inclusive scan over 1024 partials
    #pragma unroll
    for (int off = 1; off < SCAN_T; off <<= 1) {
        int mine = sums[t];
        int add  = (t >= off) ? sums[t - off] : 0;
        __syncthreads();
        sums[t] = mine + add;
        __syncthreads();
    }

    int run = (t > 0) ? sums[t - 1] : 0;   // exclusive prefix for this chunk
    for (int i = begin; i < end; i++) {
        g_colptr[i] = run;
        g_cursor[i] = run;
        run += g_ecount[i];
    }
    if (t == 0) g_colptr[NN] = sums[SCAN_T - 1];
}

__global__ void k_scatter(const int* __restrict__ row, const int* __restrict__ col) {
    int e = blockIdx.x * blockDim.x + threadIdx.x;
    if (e < EE) {
        int p = atomicAdd(&g_cursor[col[e]], 1);
        g_csr_row[p] = row[e];
    }
}

// g0 = dinv .* x
__global__ void k_scale_x(const float4* __restrict__ x, float4* __restrict__ g0) {
    int t = blockIdx.x * blockDim.x + threadIdx.x;
    if (t < NN * DV) {
        int v = t / DV;
        float s = g_dinv[v];
        float4 a = x[t];
        g0[t] = make_float4(a.x * s, a.y * s, a.z * s, a.w * s);
    }
}

// ---------------- propagation ----------------
// Warp per node. Lane layout: el = lane>>2 (8 edge slots), q = lane&3.
// Each lane accumulates float4 chunks q, q+4, q+8 (3 accumulators).
// Butterfly shfl_xor(4,8,16) reduces across the 8 edge slots.
template <bool WRITE_H>
__global__ void __launch_bounds__(256) k_propagate(const float4* __restrict__ gin,
                                                   const float4* __restrict__ x,
                                                   float4* __restrict__ gout) {
    int gwarp = (blockIdx.x * blockDim.x + threadIdx.x) >> 5;
    int lane  = threadIdx.x & 31;
    if (gwarp >= NN) return;
    int v = gwarp;

    int el = lane >> 2;
    int q  = lane & 3;

    int s    = g_colptr[v];
    int eend = g_colptr[v + 1];

    float4 a0 = make_float4(0.f, 0.f, 0.f, 0.f);
    float4 a1 = a0, a2 = a0;

    for (int b = s; b < eend; b += 8) {
        int e = b + el;
        if (e < eend) {
            int r = g_csr_row[e];
            const float4* gr = gin + (size_t)r * DV;
            a0 = f4add(a0, __ldg(&gr[q]));
            a1 = f4add(a1, __ldg(&gr[q + 4]));
            a2 = f4add(a2, __ldg(&gr[q + 8]));
        }
    }

    // reduce across edge slots (lane bits 2..4)
    #pragma unroll
    for (int off = 4; off <= 16; off <<= 1) {
        a0.x += __shfl_xor_sync(0xffffffffu, a0.x, off);
        a0.y += __shfl_xor_sync(0xffffffffu, a0.y, off);
        a0.z += __shfl_xor_sync(0xffffffffu, a0.z, off);
        a0.w += __shfl_xor_sync(0xffffffffu, a0.w, off);
        a1.x += __shfl_xor_sync(0xffffffffu, a1.x, off);
        a1.y += __shfl_xor_sync(0xffffffffu, a1.y, off);
        a1.z += __shfl_xor_sync(0xffffffffu, a1.z, off);
        a1.w += __shfl_xor_sync(0xffffffffu, a1.w, off);
        a2.x += __shfl_xor_sync(0xffffffffu, a2.x, off);
        a2.y += __shfl_xor_sync(0xffffffffu, a2.y, off);
        a2.z += __shfl_xor_sync(0xffffffffu, a2.z, off);
        a2.w += __shfl_xor_sync(0xffffffffu, a2.w, off);
    }

    // lanes 0..11 each own output chunk `lane`
    if (lane < 12) {
        int sel = lane >> 2;                 // which accumulator
        float4 val = (sel == 0) ? a0 : ((sel == 1) ? a1 : a2);

        float  di = g_dinv[v];
        size_t idx = (size_t)v * DV + lane;
        float4 gv = __ldg(&gin[idx]);        // self loop: + g[v]
        float4 xx = __ldg(&x[idx]);

        float4 h;
        h.x = (1.0f - ALPHA) * (di * (val.x + gv.x)) + ALPHA * xx.x;
        h.y = (1.0f - ALPHA) * (di * (val.y + gv.y)) + ALPHA * xx.y;
        h.z = (1.0f - ALPHA) * (di * (val.z + gv.z)) + ALPHA * xx.z;
        h.w = (1.0f - ALPHA) * (di * (val.w + gv.w)) + ALPHA * xx.w;

        if (!WRITE_H) {                      // store g = dinv * h for next step
            h.x *= di; h.y *= di; h.z *= di; h.w *= di;
        }
        gout[idx] = h;
    }
}

// ---------------- launch ----------------
extern "C" void kernel_launch(void* const* d_in, const int* in_sizes, int n_in,
                              void* d_out, int out_size) {
    const float4* x  = (const float4*)d_in[0];
    const int*    ei = (const int*)d_in[1];
    const int* row = ei;          // edge_index[0]
    const int* col = ei + EE;     // edge_index[1]
    float4* out = (float4*)d_out;

    float4 *pA, *pB;
    cudaGetSymbolAddress((void**)&pA, g_bufA);
    cudaGetSymbolAddress((void**)&pB, g_bufB);

    k_zero_counts<<<(NN + 255) / 256, 256>>>();
    k_hist<<<(EE + 255) / 256, 256>>>(col);
    k_dinv<<<(NN + 255) / 256, 256>>>();
    k_scan<<<1, SCAN_T>>>();
    k_scatter<<<(EE + 255) / 256, 256>>>(row, col);
    k_scale_x<<<(NN * DV + 255) / 256, 256>>>(x, pA);

    const int PBLK = 256;                       // 8 warps = 8 nodes per block
    const int PGRID = (NN + 7) / 8;             // 12500
    k_propagate<false><<<PGRID, PBLK>>>(pA, x, pB);  // step 1
    k_propagate<false><<<PGRID, PBLK>>>(pB, x, pA);  // step 2
    k_propagate<false><<<PGRID, PBLK>>>(pA, x, pB);  // step 3
    k_propagate<false><<<PGRID, PBLK>>>(pB, x, pA);  // step 4
    k_propagate<true ><<<PGRID, PBLK>>>(pA, x, out); // step 5 -> h
}

// round 3
// speedup vs baseline: 1.5703x; 1.5703x over previous
#include <cuda_runtime.h>

// APPNP: h_{k+1} = (1-a) * Dinv(A+I)Dinv * h_k + a * x,  K=5, a=0.8
// With g = dinv .* h, aggregation is m[v] = dinv[v]*(g[v] + sum_{e:col=v} g[row_e]).
// CSR built with ATOMIC SEGMENT ALLOCATION (no prefix scan): segments are
// contiguous but in arbitrary node order, which is all the gather needs.

#define NN 100000
#define EE 1600000
#define DD 48
#define DV 12           // float4 chunks per row
#define ALPHA 0.8f

// ---------------- device scratch (static, no allocation) ----------------
__device__ int    g_ecount[NN];
__device__ float  g_dinv[NN];
__device__ int    g_colstart[NN];
__device__ int    g_cursor[NN];
__device__ int    g_total;
__device__ int    g_csr_row[EE];
__device__ float4 g_bufA[NN * DV];
__device__ float4 g_bufB[NN * DV];

static __device__ __forceinline__ float4 f4add(float4 a, float4 b) {
    return make_float4(a.x + b.x, a.y + b.y, a.z + b.z, a.w + b.w);
}

// ---------------- preprocessing ----------------
__global__ void k_zero_counts() {
    int v = blockIdx.x * blockDim.x + threadIdx.x;
    if (v < NN) g_ecount[v] = 0;
    if (v == 0) g_total = 0;
}

__global__ void k_hist(const int* __restrict__ col) {
    int e = blockIdx.x * blockDim.x + threadIdx.x;
    if (e < EE) atomicAdd(&g_ecount[col[e]], 1);
}

// Claim a contiguous segment per node via one global atomic; also compute dinv.
__global__ void k_alloc() {
    int v = blockIdx.x * blockDim.x + threadIdx.x;
    if (v < NN) {
        int c = g_ecount[v];
        int p = atomicAdd(&g_total, c);
        g_colstart[v] = p;
        g_cursor[v]   = p;
        g_dinv[v]     = rsqrtf((float)(c + 1));   // +1 self loop
    }
}

__global__ void k_scatter(const int* __restrict__ row, const int* __restrict__ col) {
    int e = blockIdx.x * blockDim.x + threadIdx.x;
    if (e < EE) {
        int p = atomicAdd(&g_cursor[col[e]], 1);
        g_csr_row[p] = row[e];
    }
}

// g0 = dinv .* x
__global__ void k_scale_x(const float4* __restrict__ x, float4* __restrict__ g0) {
    int t = blockIdx.x * blockDim.x + threadIdx.x;
    if (t < NN * DV) {
        int v = t / DV;
        float s = g_dinv[v];
        float4 a = x[t];
        g0[t] = make_float4(a.x * s, a.y * s, a.z * s, a.w * s);
    }
}

// ---------------- propagation ----------------
// Warp per node. Lane layout: el = lane>>2 (8 edge slots), q = lane&3.
// Each lane holds 3 float4 accumulators (chunks q, q+4, q+8).
template <bool WRITE_H>
__global__ void __launch_bounds__(256) k_propagate(const float4* __restrict__ gin,
                                                   const float4* __restrict__ x,
                                                   float4* __restrict__ gout) {
    int gwarp = (blockIdx.x * blockDim.x + threadIdx.x) >> 5;
    int lane  = threadIdx.x & 31;
    if (gwarp >= NN) return;
    int v = gwarp;

    int el = lane >> 2;
    int q  = lane & 3;

    int s    = g_colstart[v];
    int eend = s + g_ecount[v];

    float4 a0 = make_float4(0.f, 0.f, 0.f, 0.f);
    float4 a1 = a0, a2 = a0;

    for (int b = s; b < eend; b += 8) {
        int e = b + el;
        if (e < eend) {
            int r = g_csr_row[e];
            const float4* gr = gin + (size_t)r * DV;
            a0 = f4add(a0, __ldg(&gr[q]));
            a1 = f4add(a1, __ldg(&gr[q + 4]));
            a2 = f4add(a2, __ldg(&gr[q + 8]));
        }
    }

    // reduce across the 8 edge slots (lane bits 2..4)
    #pragma unroll
    for (int off = 4; off <= 16; off <<= 1) {
        a0.x += __shfl_xor_sync(0xffffffffu, a0.x, off);
        a0.y += __shfl_xor_sync(0xffffffffu, a0.y, off);
        a0.z += __shfl_xor_sync(0xffffffffu, a0.z, off);
        a0.w += __shfl_xor_sync(0xffffffffu, a0.w, off);
        a1.x += __shfl_xor_sync(0xffffffffu, a1.x, off);
        a1.y += __shfl_xor_sync(0xffffffffu, a1.y, off);
        a1.z += __shfl_xor_sync(0xffffffffu, a1.z, off);
        a1.w += __shfl_xor_sync(0xffffffffu, a1.w, off);
        a2.x += __shfl_xor_sync(0xffffffffu, a2.x, off);
        a2.y += __shfl_xor_sync(0xffffffffu, a2.y, off);
        a2.z += __shfl_xor_sync(0xffffffffu, a2.z, off);
        a2.w += __shfl_xor_sync(0xffffffffu, a2.w, off);
    }

    // lanes 0..11 each own output chunk `lane`
    if (lane < 12) {
        int sel = lane >> 2;
        float4 val = (sel == 0) ? a0 : ((sel == 1) ? a1 : a2);

        float  di = g_dinv[v];
        size_t idx = (size_t)v * DV + lane;
        float4 gv = __ldg(&gin[idx]);        // self loop: + g[v]
        float4 xx = __ldg(&x[idx]);

        float4 h;
        h.x = (1.0f - ALPHA) * (di * (val.x + gv.x)) + ALPHA * xx.x;
        h.y = (1.0f - ALPHA) * (di * (val.y + gv.y)) + ALPHA * xx.y;
        h.z = (1.0f - ALPHA) * (di * (val.z + gv.z)) + ALPHA * xx.z;
        h.w = (1.0f - ALPHA) * (di * (val.w + gv.w)) + ALPHA * xx.w;

        if (!WRITE_H) {                      // store g = dinv * h for next step
            h.x *= di; h.y *= di; h.z *= di; h.w *= di;
        }
        gout[idx] = h;
    }
}

// ---------------- launch ----------------
extern "C" void kernel_launch(void* const* d_in, const int* in_sizes, int n_in,
                              void* d_out, int out_size) {
    const float4* x  = (const float4*)d_in[0];
    const int*    ei = (const int*)d_in[1];
    const int* row = ei;          // edge_index[0]
    const int* col = ei + EE;     // edge_index[1]
    float4* out = (float4*)d_out;

    float4 *pA, *pB;
    cudaGetSymbolAddress((void**)&pA, g_bufA);
    cudaGetSymbolAddress((void**)&pB, g_bufB);

    k_zero_counts<<<(NN + 255) / 256, 256>>>();
    k_hist<<<(EE + 255) / 256, 256>>>(col);
    k_alloc<<<(NN + 255) / 256, 256>>>();
    k_scatter<<<(EE + 255) / 256, 256>>>(row, col);
    k_scale_x<<<(NN * DV + 255) / 256, 256>>>(x, pA);

    const int PBLK = 256;                       // 8 warps = 8 nodes per block
    const int PGRID = (NN + 7) / 8;             // 12500
    k_propagate<false><<<PGRID, PBLK>>>(pA, x, pB);  // step 1
    k_propagate<false><<<PGRID, PBLK>>>(pB, x, pA);  // step 2
    k_propagate<false><<<PGRID, PBLK>>>(pA, x, pB);  // step 3
    k_propagate<false><<<PGRID, PBLK>>>(pB, x, pA);  // step 4
    k_propagate<true ><<<PGRID, PBLK>>>(pA, x, out); // step 5 -> h
}